// round 3
// baseline (speedup 1.0000x reference)
#include <cuda_runtime.h>
#include <cstdint>

#define HW 1024
#define PLANE (HW * HW)
#define BMAX 16

// Ping-pong scratch for the low-pass images (allocation-free rule).
static __device__ float g_lowA[BMAX * PLANE];
static __device__ float g_lowB[BMAX * PLANE];

__device__ __forceinline__ int refl(int i) {
    // jnp.pad 'symmetric': -1 -> 0, -2 -> 1, N -> N-1
    if (i < 0)    i = -1 - i;
    if (i >= HW)  i = 2 * HW - 1 - i;
    return i;
}

// One starlet scale. Vertical dilated-by-D conv == plain 5-tap conv on each of
// D row-subsampled sub-images. Block = 256 threads = one full 1024-float row.
// blockIdx.y = residue class, blockIdx.x = strip of S sub-rows, blockIdx.z = batch.
//
// Register pipeline: two 4-deep float4 queues p[]/nl[] hold the last 8 loaded
// sub-rows; each slab of R=4 output rows needs exactly 4 new LDG.128 (batched,
// MLP=4). Vertical result -> smem slab; horizontal 5-tap from smem; coeff uses
// the register-held raw center (p[2],p[3],nl[0],nl[1]).
template<int D, int SRC, int DST>
__global__ __launch_bounds__(256, 4)
void starlet_stream(const float* __restrict__ ext_in,
                    const float* __restrict__ norms,
                    int scale,
                    float* __restrict__ coeff_out)
{
    constexpr int S = 32;   // sub-rows per block
    constexpr int R = 4;    // sub-rows per smem slab
    constexpr float W0 = 1.0f / 16.0f;
    constexpr float W1 = 1.0f / 4.0f;
    constexpr float W2 = 3.0f / 8.0f;

    __shared__ __align__(16) float sm[R][HW + 4];

    const int t     = threadIdx.x;        // float4 column 0..255
    const int resid = blockIdx.y;         // residue class
    const int s0    = blockIdx.x * S;     // first sub-row of strip
    const int b     = blockIdx.z;

    const float* src  = (SRC == 0) ? ext_in : (SRC == 1 ? g_lowA : g_lowB);
    const float* simg = src + (size_t)b * PLANE;
    float* lowdst = (DST == 1) ? g_lowA : (DST == 2 ? g_lowB : nullptr);
    if (DST != 0) lowdst += (size_t)b * PLANE;

    const int x4 = 4 * t;
    const float inv = 1.0f / norms[scale];

    auto ldrow = [&](int s) -> float4 {
        const int f = refl(resid + D * s);   // full-image row, reflected
        return *reinterpret_cast<const float4*>(simg + (size_t)f * HW + x4);
    };

    auto vcomb = [&](const float4& a, const float4& bb, const float4& c,
                     const float4& d, const float4& e) -> float4 {
        float4 v;
        v.x = W0 * (a.x + e.x) + W1 * (bb.x + d.x) + W2 * c.x;
        v.y = W0 * (a.y + e.y) + W1 * (bb.y + d.y) + W2 * c.y;
        v.z = W0 * (a.z + e.z) + W1 * (bb.z + d.z) + W2 * c.z;
        v.w = W0 * (a.w + e.w) + W1 * (bb.w + d.w) + W2 * c.w;
        return v;
    };

    // p[] holds sub-rows base-2..base+1 for the upcoming slab (base = s0 initially).
    float4 p0 = ldrow(s0 - 2);
    float4 p1 = ldrow(s0 - 1);
    float4 p2 = ldrow(s0);
    float4 p3 = ldrow(s0 + 1);

    #pragma unroll
    for (int slab = 0; slab < S / R; slab++) {
        const int base = s0 + slab * R;

        // ---- batched loads for this slab: rows base+2..base+5 (MLP=4) ----
        float4 n0 = ldrow(base + 2);
        float4 n1 = ldrow(base + 3);
        float4 n2 = ldrow(base + 4);
        float4 n3 = ldrow(base + 5);

        // ---- vertical 5-tap into smem ----
        *reinterpret_cast<float4*>(&sm[0][x4]) = vcomb(p0, p1, p2, p3, n0);
        *reinterpret_cast<float4*>(&sm[1][x4]) = vcomb(p1, p2, p3, n0, n1);
        *reinterpret_cast<float4*>(&sm[2][x4]) = vcomb(p2, p3, n0, n1, n2);
        *reinterpret_cast<float4*>(&sm[3][x4]) = vcomb(p3, n0, n1, n2, n3);
        __syncthreads();

        // raw centers for the 4 output rows of this slab
        const float4 raws[R] = { p2, p3, n0, n1 };

        // ---- horizontal 5-tap (dilated by D along x) from smem ----
        #pragma unroll
        for (int r = 0; r < R; r++) {
            const int yf = resid + D * (base + r);     // full-image output row
            float4 low;

            if constexpr (D >= 4) {
                constexpr int G = D / 4;               // tap offset in f4 groups
                if (t >= 2 * G && t <= 255 - 2 * G) {
                    const float4 a  = *reinterpret_cast<const float4*>(&sm[r][x4 - 8 * G]);
                    const float4 bb = *reinterpret_cast<const float4*>(&sm[r][x4 - 4 * G]);
                    const float4 c  = *reinterpret_cast<const float4*>(&sm[r][x4]);
                    const float4 d  = *reinterpret_cast<const float4*>(&sm[r][x4 + 4 * G]);
                    const float4 e  = *reinterpret_cast<const float4*>(&sm[r][x4 + 8 * G]);
                    low = vcomb(a, bb, c, d, e);
                } else {
                    float lo[4];
                    #pragma unroll
                    for (int j = 0; j < 4; j++) {
                        const int e0 = x4 + j;
                        auto g = [&](int m) -> float {
                            int e = e0 + m;
                            if (e < 0)    e = -1 - e;
                            if (e >= HW)  e = 2 * HW - 1 - e;
                            return sm[r][e];
                        };
                        lo[j] = W0 * (g(-2 * D) + g(2 * D))
                              + W1 * (g(-D) + g(D)) + W2 * g(0);
                    }
                    low.x = lo[0]; low.y = lo[1]; low.z = lo[2]; low.w = lo[3];
                }
            } else {
                if (t >= 1 && t <= 254) {
                    float fl[12];
                    *reinterpret_cast<float4*>(&fl[0]) = *reinterpret_cast<const float4*>(&sm[r][x4 - 4]);
                    *reinterpret_cast<float4*>(&fl[4]) = *reinterpret_cast<const float4*>(&sm[r][x4]);
                    *reinterpret_cast<float4*>(&fl[8]) = *reinterpret_cast<const float4*>(&sm[r][x4 + 4]);
                    float lo[4];
                    #pragma unroll
                    for (int j = 0; j < 4; j++) {
                        lo[j] = W0 * (fl[4 + j - 2 * D] + fl[4 + j + 2 * D])
                              + W1 * (fl[4 + j - D]     + fl[4 + j + D])
                              + W2 *  fl[4 + j];
                    }
                    low.x = lo[0]; low.y = lo[1]; low.z = lo[2]; low.w = lo[3];
                } else {
                    float lo[4];
                    #pragma unroll
                    for (int j = 0; j < 4; j++) {
                        const int e0 = x4 + j;
                        auto g = [&](int m) -> float {
                            int e = e0 + m;
                            if (e < 0)    e = -1 - e;
                            if (e >= HW)  e = 2 * HW - 1 - e;
                            return sm[r][e];
                        };
                        lo[j] = W0 * (g(-2 * D) + g(2 * D))
                              + W1 * (g(-D) + g(D)) + W2 * g(0);
                    }
                    low.x = lo[0]; low.y = lo[1]; low.z = lo[2]; low.w = lo[3];
                }
            }

            float4 cf;
            cf.x = (raws[r].x - low.x) * inv;
            cf.y = (raws[r].y - low.y) * inv;
            cf.z = (raws[r].z - low.z) * inv;
            cf.w = (raws[r].w - low.w) * inv;

            const size_t o = ((size_t)b * HW + yf) * HW + x4;
            *reinterpret_cast<float4*>(coeff_out + o) = cf;
            if (DST != 0) {
                *reinterpret_cast<float4*>(lowdst + (size_t)yf * HW + x4) = low;
            }
        }
        __syncthreads();

        // advance pipeline
        p0 = n0; p1 = n1; p2 = n2; p3 = n3;
    }
}

extern "C" void kernel_launch(void* const* d_in, const int* in_sizes, int n_in,
                              void* d_out, int out_size)
{
    int img_idx = 0, nrm_idx = 1;
    if (n_in >= 2 && in_sizes[0] == 4) { img_idx = 1; nrm_idx = 0; }

    const float* image = (const float*)d_in[img_idx];
    const float* norms = (const float*)d_in[nrm_idx];
    float* out = (float*)d_out;

    int B = in_sizes[img_idx] / PLANE;
    if (B < 1) B = 1;
    if (B > BMAX) B = BMAX;
    const size_t plane_all = (size_t)B * PLANE;

    const dim3 block(256);
    // grid: x = strips of 32 sub-rows, y = D residues, z = batch
    const dim3 g1(HW / (1 * 32), 1, B);
    const dim3 g2(HW / (2 * 32), 2, B);
    const dim3 g4(HW / (4 * 32), 4, B);
    const dim3 g8(HW / (8 * 32), 8, B);

    starlet_stream<1, 0, 1><<<g1, block>>>(image, norms, 0, out + 0 * plane_all);
    starlet_stream<2, 1, 2><<<g2, block>>>(image, norms, 1, out + 1 * plane_all);
    starlet_stream<4, 2, 1><<<g4, block>>>(image, norms, 2, out + 2 * plane_all);
    starlet_stream<8, 1, 0><<<g8, block>>>(image, norms, 3, out + 3 * plane_all);
}

// round 4
// speedup vs baseline: 1.0232x; 1.0232x over previous
#include <cuda_runtime.h>
#include <cstdint>

#define HW 1024
#define PLANE (HW * HW)
#define BMAX 16

// Ping-pong scratch for the low-pass images (allocation-free rule).
static __device__ float g_lowA[BMAX * PLANE];
static __device__ float g_lowB[BMAX * PLANE];

__device__ __forceinline__ int refl(int i) {
    // jnp.pad 'symmetric': -1 -> 0, -2 -> 1, N -> N-1
    if (i < 0)    i = -1 - i;
    if (i >= HW)  i = 2 * HW - 1 - i;
    return i;
}

// One starlet scale. Vertical dilated-by-D conv == plain 5-tap conv on each of
// D row-subsampled sub-images. Block = 256 threads = one full 1024-float row.
// blockIdx.y = residue class, blockIdx.x = strip of S sub-rows, blockIdx.z = batch.
//
// Software-pipelined: while the horizontal phase of slab k runs, slab k+1's
// four LDG.128 are already in flight (issued before the barrier). Double-
// buffered smem gives exactly one __syncthreads per slab.
template<int D, int SRC, int DST>
__global__ __launch_bounds__(256, 4)
void starlet_stream(const float* __restrict__ ext_in,
                    const float* __restrict__ norms,
                    int scale,
                    float* __restrict__ coeff_out)
{
    constexpr int S = 32;   // sub-rows per block
    constexpr int R = 4;    // sub-rows per smem slab
    constexpr int NSLAB = S / R;
    constexpr float W0 = 1.0f / 16.0f;
    constexpr float W1 = 1.0f / 4.0f;
    constexpr float W2 = 3.0f / 8.0f;

    __shared__ __align__(16) float sm[2][R][HW + 4];

    const int t     = threadIdx.x;        // float4 column 0..255
    const int resid = blockIdx.y;         // residue class
    const int s0    = blockIdx.x * S;     // first sub-row of strip
    const int b     = blockIdx.z;

    const float* src  = (SRC == 0) ? ext_in : (SRC == 1 ? g_lowA : g_lowB);
    const float* simg = src + (size_t)b * PLANE;
    float* lowdst = (DST == 1) ? g_lowA : (DST == 2 ? g_lowB : nullptr);
    if (DST != 0) lowdst += (size_t)b * PLANE;

    const int x4 = 4 * t;
    const float inv = 1.0f / norms[scale];

    auto ldrow = [&](int s) -> float4 {
        const int f = refl(resid + D * s);   // full-image row, reflected
        return *reinterpret_cast<const float4*>(simg + (size_t)f * HW + x4);
    };

    auto vcomb = [&](const float4& a, const float4& bb, const float4& c,
                     const float4& d, const float4& e) -> float4 {
        float4 v;
        v.x = W0 * (a.x + e.x) + W1 * (bb.x + d.x) + W2 * c.x;
        v.y = W0 * (a.y + e.y) + W1 * (bb.y + d.y) + W2 * c.y;
        v.z = W0 * (a.z + e.z) + W1 * (bb.z + d.z) + W2 * c.z;
        v.w = W0 * (a.w + e.w) + W1 * (bb.w + d.w) + W2 * c.w;
        return v;
    };

    // Pipeline state: p0..p3 = sub-rows base-2..base+1, n0..n3 = base+2..base+5.
    float4 p0 = ldrow(s0 - 2);
    float4 p1 = ldrow(s0 - 1);
    float4 p2 = ldrow(s0);
    float4 p3 = ldrow(s0 + 1);
    float4 n0 = ldrow(s0 + 2);
    float4 n1 = ldrow(s0 + 3);
    float4 n2 = ldrow(s0 + 4);
    float4 n3 = ldrow(s0 + 5);

    #pragma unroll
    for (int slab = 0; slab < NSLAB; slab++) {
        const int base = s0 + slab * R;
        const int buf  = slab & 1;

        // ---- vertical 5-tap into smem slab ----
        *reinterpret_cast<float4*>(&sm[buf][0][x4]) = vcomb(p0, p1, p2, p3, n0);
        *reinterpret_cast<float4*>(&sm[buf][1][x4]) = vcomb(p1, p2, p3, n0, n1);
        *reinterpret_cast<float4*>(&sm[buf][2][x4]) = vcomb(p2, p3, n0, n1, n2);
        *reinterpret_cast<float4*>(&sm[buf][3][x4]) = vcomb(p3, n0, n1, n2, n3);

        // Save raw centers 0,1; advance pipeline (centers 2,3 live on as p0,p1).
        const float4 q2 = p2, q3 = p3;
        p0 = n0; p1 = n1; p2 = n2; p3 = n3;

        // ---- prefetch next slab's rows: in flight across the barrier ----
        if (slab + 1 < NSLAB) {
            n0 = ldrow(base + 6);
            n1 = ldrow(base + 7);
            n2 = ldrow(base + 8);
            n3 = ldrow(base + 9);
        }

        __syncthreads();

        const float4 raws[R] = { q2, q3, p0, p1 };

        // ---- horizontal 5-tap (dilated by D along x) from smem ----
        #pragma unroll
        for (int r = 0; r < R; r++) {
            const int yf = resid + D * (base + r);     // full-image output row
            float4 low;

            if constexpr (D >= 4) {
                constexpr int G = D / 4;               // tap offset in f4 groups
                if (t >= 2 * G && t <= 255 - 2 * G) {
                    const float4 a  = *reinterpret_cast<const float4*>(&sm[buf][r][x4 - 8 * G]);
                    const float4 bb = *reinterpret_cast<const float4*>(&sm[buf][r][x4 - 4 * G]);
                    const float4 c  = *reinterpret_cast<const float4*>(&sm[buf][r][x4]);
                    const float4 d  = *reinterpret_cast<const float4*>(&sm[buf][r][x4 + 4 * G]);
                    const float4 e  = *reinterpret_cast<const float4*>(&sm[buf][r][x4 + 8 * G]);
                    low = vcomb(a, bb, c, d, e);
                } else {
                    float lo[4];
                    #pragma unroll
                    for (int j = 0; j < 4; j++) {
                        const int e0 = x4 + j;
                        auto g = [&](int m) -> float {
                            int e = e0 + m;
                            if (e < 0)    e = -1 - e;
                            if (e >= HW)  e = 2 * HW - 1 - e;
                            return sm[buf][r][e];
                        };
                        lo[j] = W0 * (g(-2 * D) + g(2 * D))
                              + W1 * (g(-D) + g(D)) + W2 * g(0);
                    }
                    low.x = lo[0]; low.y = lo[1]; low.z = lo[2]; low.w = lo[3];
                }
            } else {
                if (t >= 1 && t <= 254) {
                    float fl[12];
                    *reinterpret_cast<float4*>(&fl[0]) = *reinterpret_cast<const float4*>(&sm[buf][r][x4 - 4]);
                    *reinterpret_cast<float4*>(&fl[4]) = *reinterpret_cast<const float4*>(&sm[buf][r][x4]);
                    *reinterpret_cast<float4*>(&fl[8]) = *reinterpret_cast<const float4*>(&sm[buf][r][x4 + 4]);
                    float lo[4];
                    #pragma unroll
                    for (int j = 0; j < 4; j++) {
                        lo[j] = W0 * (fl[4 + j - 2 * D] + fl[4 + j + 2 * D])
                              + W1 * (fl[4 + j - D]     + fl[4 + j + D])
                              + W2 *  fl[4 + j];
                    }
                    low.x = lo[0]; low.y = lo[1]; low.z = lo[2]; low.w = lo[3];
                } else {
                    float lo[4];
                    #pragma unroll
                    for (int j = 0; j < 4; j++) {
                        const int e0 = x4 + j;
                        auto g = [&](int m) -> float {
                            int e = e0 + m;
                            if (e < 0)    e = -1 - e;
                            if (e >= HW)  e = 2 * HW - 1 - e;
                            return sm[buf][r][e];
                        };
                        lo[j] = W0 * (g(-2 * D) + g(2 * D))
                              + W1 * (g(-D) + g(D)) + W2 * g(0);
                    }
                    low.x = lo[0]; low.y = lo[1]; low.z = lo[2]; low.w = lo[3];
                }
            }

            float4 cf;
            cf.x = (raws[r].x - low.x) * inv;
            cf.y = (raws[r].y - low.y) * inv;
            cf.z = (raws[r].z - low.z) * inv;
            cf.w = (raws[r].w - low.w) * inv;

            const size_t o = ((size_t)b * HW + yf) * HW + x4;
            *reinterpret_cast<float4*>(coeff_out + o) = cf;
            if (DST != 0) {
                *reinterpret_cast<float4*>(lowdst + (size_t)yf * HW + x4) = low;
            }
        }
        // no trailing barrier: double-buffered smem
    }
}

extern "C" void kernel_launch(void* const* d_in, const int* in_sizes, int n_in,
                              void* d_out, int out_size)
{
    int img_idx = 0, nrm_idx = 1;
    if (n_in >= 2 && in_sizes[0] == 4) { img_idx = 1; nrm_idx = 0; }

    const float* image = (const float*)d_in[img_idx];
    const float* norms = (const float*)d_in[nrm_idx];
    float* out = (float*)d_out;

    int B = in_sizes[img_idx] / PLANE;
    if (B < 1) B = 1;
    if (B > BMAX) B = BMAX;
    const size_t plane_all = (size_t)B * PLANE;

    const dim3 block(256);
    // grid: x = strips of 32 sub-rows, y = D residues, z = batch
    const dim3 g1(HW / (1 * 32), 1, B);
    const dim3 g2(HW / (2 * 32), 2, B);
    const dim3 g4(HW / (4 * 32), 4, B);
    const dim3 g8(HW / (8 * 32), 8, B);

    starlet_stream<1, 0, 1><<<g1, block>>>(image, norms, 0, out + 0 * plane_all);
    starlet_stream<2, 1, 2><<<g2, block>>>(image, norms, 1, out + 1 * plane_all);
    starlet_stream<4, 2, 1><<<g4, block>>>(image, norms, 2, out + 2 * plane_all);
    starlet_stream<8, 1, 0><<<g8, block>>>(image, norms, 3, out + 3 * plane_all);
}

// round 5
// speedup vs baseline: 1.1042x; 1.0792x over previous
#include <cuda_runtime.h>
#include <cstdint>

#define HW 1024
#define PLANE (HW * HW)
#define BMAX 16

// Ping-pong scratch for the low-pass images (allocation-free rule).
static __device__ float g_lowA[BMAX * PLANE];
static __device__ float g_lowB[BMAX * PLANE];

__device__ __forceinline__ int refl(int i) {
    // jnp.pad 'symmetric': -1 -> 0, -2 -> 1, N -> N-1
    if (i < 0)    i = -1 - i;
    if (i >= HW)  i = 2 * HW - 1 - i;
    return i;
}

// One starlet scale. Vertical dilated-by-D conv == plain 5-tap conv on each of
// D row-subsampled sub-images. Block = 256 threads = one full 1024-float row.
// blockIdx.y = residue class, blockIdx.x = strip of S sub-rows, blockIdx.z = batch.
//
// R=2 slabs: vertical results v0,v1 stay in REGISTERS across the barrier and
// serve as the horizontal center tap (LDS 5->4 for D>=4, 3->2 for D<=2).
// Next slab's two LDG.128 issue before the barrier (in flight over horizontal).
// Coeff stores use __stcs (streaming) so the low image stays resident in L2
// for the next scale's read.
template<int D, int SRC, int DST>
__global__ __launch_bounds__(256, 4)
void starlet_stream(const float* __restrict__ ext_in,
                    const float* __restrict__ norms,
                    int scale,
                    float* __restrict__ coeff_out)
{
    constexpr int S = 32;     // sub-rows per block
    constexpr int R = 2;      // sub-rows per smem slab
    constexpr int NSLAB = S / R;
    constexpr float W0 = 1.0f / 16.0f;
    constexpr float W1 = 1.0f / 4.0f;
    constexpr float W2 = 3.0f / 8.0f;

    __shared__ __align__(16) float sm[2][R][HW + 4];

    const int t     = threadIdx.x;        // float4 column 0..255
    const int resid = blockIdx.y;         // residue class
    const int s0    = blockIdx.x * S;     // first sub-row of strip
    const int b     = blockIdx.z;

    const float* src  = (SRC == 0) ? ext_in : (SRC == 1 ? g_lowA : g_lowB);
    const float* simg = src + (size_t)b * PLANE;
    float* lowdst = (DST == 1) ? g_lowA : (DST == 2 ? g_lowB : nullptr);
    if (DST != 0) lowdst += (size_t)b * PLANE;

    const int x4 = 4 * t;
    const float inv = 1.0f / norms[scale];

    auto ldrow = [&](int s) -> float4 {
        const int f = refl(resid + D * s);   // full-image row, reflected
        return *reinterpret_cast<const float4*>(simg + (size_t)f * HW + x4);
    };

    auto vcomb = [&](const float4& a, const float4& bb, const float4& c,
                     const float4& d, const float4& e) -> float4 {
        float4 v;
        v.x = W0 * (a.x + e.x) + W1 * (bb.x + d.x) + W2 * c.x;
        v.y = W0 * (a.y + e.y) + W1 * (bb.y + d.y) + W2 * c.y;
        v.z = W0 * (a.z + e.z) + W1 * (bb.z + d.z) + W2 * c.z;
        v.w = W0 * (a.w + e.w) + W1 * (bb.w + d.w) + W2 * c.w;
        return v;
    };

    // Window w0..w3 = sub-rows base-2..base+1; n0,n1 = base+2, base+3.
    float4 w0 = ldrow(s0 - 2);
    float4 w1 = ldrow(s0 - 1);
    float4 w2 = ldrow(s0);
    float4 w3 = ldrow(s0 + 1);
    float4 n0 = ldrow(s0 + 2);
    float4 n1 = ldrow(s0 + 3);

    #pragma unroll 4
    for (int slab = 0; slab < NSLAB; slab++) {
        const int base = s0 + slab * R;
        const int buf  = slab & 1;

        // ---- vertical 5-tap; results stay in regs as horizontal center taps ----
        const float4 v0 = vcomb(w0, w1, w2, w3, n0);   // row base
        const float4 v1 = vcomb(w1, w2, w3, n0, n1);   // row base+1
        *reinterpret_cast<float4*>(&sm[buf][0][x4]) = v0;
        *reinterpret_cast<float4*>(&sm[buf][1][x4]) = v1;

        // shift window to rows base..base+3 (raw centers = new w0,w1)
        w0 = w2; w1 = w3; w2 = n0; w3 = n1;

        // prefetch next slab's rows (in flight across the barrier)
        if (slab + 1 < NSLAB) {
            n0 = ldrow(base + 4);
            n1 = ldrow(base + 5);
        }

        __syncthreads();

        // ---- horizontal 5-tap (dilated by D along x), center from register ----
        #pragma unroll
        for (int r = 0; r < R; r++) {
            const float4 vc  = (r == 0) ? v0 : v1;     // own vertical result
            const float4 raw = (r == 0) ? w0 : w1;     // raw center value
            const int yf = resid + D * (base + r);     // full-image output row
            float4 low;

            if constexpr (D >= 4) {
                constexpr int G = D / 4;               // tap offset in f4 groups
                if (t >= 2 * G && t <= 255 - 2 * G) {
                    const float4 a  = *reinterpret_cast<const float4*>(&sm[buf][r][x4 - 8 * G]);
                    const float4 bb = *reinterpret_cast<const float4*>(&sm[buf][r][x4 - 4 * G]);
                    const float4 d  = *reinterpret_cast<const float4*>(&sm[buf][r][x4 + 4 * G]);
                    const float4 e  = *reinterpret_cast<const float4*>(&sm[buf][r][x4 + 8 * G]);
                    low = vcomb(a, bb, vc, d, e);
                } else {
                    float lo[4];
                    #pragma unroll
                    for (int j = 0; j < 4; j++) {
                        const int e0 = x4 + j;
                        auto g = [&](int m) -> float {
                            int e = e0 + m;
                            if (e < 0)    e = -1 - e;
                            if (e >= HW)  e = 2 * HW - 1 - e;
                            return sm[buf][r][e];
                        };
                        lo[j] = W0 * (g(-2 * D) + g(2 * D))
                              + W1 * (g(-D) + g(D)) + W2 * g(0);
                    }
                    low.x = lo[0]; low.y = lo[1]; low.z = lo[2]; low.w = lo[3];
                }
            } else {
                if (t >= 1 && t <= 254) {
                    float fl[12];
                    *reinterpret_cast<float4*>(&fl[0]) = *reinterpret_cast<const float4*>(&sm[buf][r][x4 - 4]);
                    fl[4] = vc.x; fl[5] = vc.y; fl[6] = vc.z; fl[7] = vc.w;
                    *reinterpret_cast<float4*>(&fl[8]) = *reinterpret_cast<const float4*>(&sm[buf][r][x4 + 4]);
                    float lo[4];
                    #pragma unroll
                    for (int j = 0; j < 4; j++) {
                        lo[j] = W0 * (fl[4 + j - 2 * D] + fl[4 + j + 2 * D])
                              + W1 * (fl[4 + j - D]     + fl[4 + j + D])
                              + W2 *  fl[4 + j];
                    }
                    low.x = lo[0]; low.y = lo[1]; low.z = lo[2]; low.w = lo[3];
                } else {
                    float lo[4];
                    #pragma unroll
                    for (int j = 0; j < 4; j++) {
                        const int e0 = x4 + j;
                        auto g = [&](int m) -> float {
                            int e = e0 + m;
                            if (e < 0)    e = -1 - e;
                            if (e >= HW)  e = 2 * HW - 1 - e;
                            return sm[buf][r][e];
                        };
                        lo[j] = W0 * (g(-2 * D) + g(2 * D))
                              + W1 * (g(-D) + g(D)) + W2 * g(0);
                    }
                    low.x = lo[0]; low.y = lo[1]; low.z = lo[2]; low.w = lo[3];
                }
            }

            float4 cf;
            cf.x = (raw.x - low.x) * inv;
            cf.y = (raw.y - low.y) * inv;
            cf.z = (raw.z - low.z) * inv;
            cf.w = (raw.w - low.w) * inv;

            const size_t o = ((size_t)b * HW + yf) * HW + x4;
            __stcs(reinterpret_cast<float4*>(coeff_out + o), cf);   // streaming: don't pollute L2
            if (DST != 0) {
                *reinterpret_cast<float4*>(lowdst + (size_t)yf * HW + x4) = low;
            }
        }
        // double-buffered smem: no trailing barrier
    }
}

extern "C" void kernel_launch(void* const* d_in, const int* in_sizes, int n_in,
                              void* d_out, int out_size)
{
    int img_idx = 0, nrm_idx = 1;
    if (n_in >= 2 && in_sizes[0] == 4) { img_idx = 1; nrm_idx = 0; }

    const float* image = (const float*)d_in[img_idx];
    const float* norms = (const float*)d_in[nrm_idx];
    float* out = (float*)d_out;

    int B = in_sizes[img_idx] / PLANE;
    if (B < 1) B = 1;
    if (B > BMAX) B = BMAX;
    const size_t plane_all = (size_t)B * PLANE;

    const dim3 block(256);
    // grid: x = strips of 32 sub-rows, y = D residues, z = batch (512 blocks/scale)
    const dim3 g1(HW / (1 * 32), 1, B);
    const dim3 g2(HW / (2 * 32), 2, B);
    const dim3 g4(HW / (4 * 32), 4, B);
    const dim3 g8(HW / (8 * 32), 8, B);

    starlet_stream<1, 0, 1><<<g1, block>>>(image, norms, 0, out + 0 * plane_all);
    starlet_stream<2, 1, 2><<<g2, block>>>(image, norms, 1, out + 1 * plane_all);
    starlet_stream<4, 2, 1><<<g4, block>>>(image, norms, 2, out + 2 * plane_all);
    starlet_stream<8, 1, 0><<<g8, block>>>(image, norms, 3, out + 3 * plane_all);
}